// round 7
// baseline (speedup 1.0000x reference)
#include <cuda_runtime.h>
#include <cstdint>

// ---------------------------------------------------------------------------
// Problem: fused top-k triple
//   x: [32,2048,1024] f32 -> top-4 desc per row            -> 262144 f32
//   y: [8,32,2048,64] f32 -> min over dim2 (2048)          -> 16384  f32
//   z: [32,4096,512]  f32 -> top-3 desc values + indices   -> 393216 + 393216 f32
// Output: concatenated float32 buffer, z indices stored as floats.
// All kernels are HBM-streaming; compute is guarded inserts (cheap).
// ---------------------------------------------------------------------------

#define INFF  (__int_as_float(0x7f800000))
#define NINFF (__int_as_float(0xff800000))

// Insert w into sorted-descending (v0 >= v1 >= v2 >= v3), keep top 4.
#define INS4(w) do { float _w = (w);                                     \
    if (_w > v3) {                                                       \
        if (_w > v1) {                                                   \
            if (_w > v0) { v3 = v2; v2 = v1; v1 = v0; v0 = _w; }         \
            else         { v3 = v2; v2 = v1; v1 = _w; }                  \
        } else {                                                         \
            if (_w > v2) { v3 = v2; v2 = _w; }                           \
            else         { v3 = _w; }                                    \
        }                                                                \
    } } while (0)

// Strictly-better with jax.lax.top_k tie-break (lower index wins on equal).
#define BETTER(a, ia, b, ib) (((a) > (b)) || (((a) == (b)) && ((ia) < (ib))))

// Insert (w, wi) into sorted-descending top-3 with indices.
#define INS3(w, wi) do { float _w = (w); int _i = (wi);                  \
    if (BETTER(_w, _i, v2, i2)) {                                        \
        if (BETTER(_w, _i, v0, i0)) {                                    \
            v2 = v1; i2 = i1; v1 = v0; i1 = i0; v0 = _w; i0 = _i;        \
        } else if (BETTER(_w, _i, v1, i1)) {                             \
            v2 = v1; i2 = i1; v1 = _w; i1 = _i;                          \
        } else { v2 = _w; i2 = _i; }                                     \
    } } while (0)

// ---------------------------------------------------------------------------
// Kernel 1: x top-4. Warp per row (65536 rows of 1024 floats).
// Lane k reads float4s at {k, k+32, ..., k+224} -> 512B coalesced per warp/iter.
// ---------------------------------------------------------------------------
__global__ __launch_bounds__(256) void kx_top4(const float* __restrict__ x,
                                               float* __restrict__ out) {
    const int row  = blockIdx.x * 8 + (threadIdx.x >> 5);
    const int lane = threadIdx.x & 31;
    const float4* p = reinterpret_cast<const float4*>(x) + (size_t)row * 256;

    float v0 = NINFF, v1 = NINFF, v2 = NINFF, v3 = NINFF;

    #pragma unroll
    for (int k = 0; k < 8; k++) {
        float4 q = p[lane + k * 32];
        INS4(q.x); INS4(q.y); INS4(q.z); INS4(q.w);
    }

    #pragma unroll
    for (int off = 16; off; off >>= 1) {
        float w0 = __shfl_xor_sync(0xffffffffu, v0, off);
        float w1 = __shfl_xor_sync(0xffffffffu, v1, off);
        float w2 = __shfl_xor_sync(0xffffffffu, v2, off);
        float w3 = __shfl_xor_sync(0xffffffffu, v3, off);
        INS4(w0); INS4(w1); INS4(w2); INS4(w3);
    }

    if (lane == 0) {
        float4 r; r.x = v0; r.y = v1; r.z = v2; r.w = v3;
        reinterpret_cast<float4*>(out)[row] = r;
    }
}

// ---------------------------------------------------------------------------
// Kernel 2a/2b: y min over dim 2.
// Phase a: grid (256 pairs, 8 chunks). Each block min-reduces 256 t-rows of
//          64 floats into __device__ scratch (load-balanced: 2048 blocks).
// Phase b: 16384 threads fold the 8 chunk-partials into the output.
// ---------------------------------------------------------------------------
__device__ float g_ypart[8 * 256 * 64];

__global__ __launch_bounds__(256) void ky_partial(const float* __restrict__ y) {
    const int pair  = blockIdx.x;      // 0..255  (b0*32 + b1)
    const int chunk = blockIdx.y;      // 0..7    (t block of 256)
    const int tid   = threadIdx.x;
    const int h4    = tid & 15;        // 16 float4 groups cover h=64
    const int tsub  = tid >> 4;        // 0..15

    const float4* p = reinterpret_cast<const float4*>(
        y + ((size_t)pair * 2048 + (size_t)chunk * 256) * 64);

    float4 m; m.x = INFF; m.y = INFF; m.z = INFF; m.w = INFF;

    #pragma unroll 4
    for (int t = tsub; t < 256; t += 16) {
        float4 q = p[t * 16 + h4];
        m.x = fminf(m.x, q.x); m.y = fminf(m.y, q.y);
        m.z = fminf(m.z, q.z); m.w = fminf(m.w, q.w);
    }

    __shared__ float4 s[256];
    s[tid] = m;
    __syncthreads();

    #pragma unroll
    for (int str = 128; str >= 16; str >>= 1) {
        if (tid < str) {
            float4 a = s[tid], b = s[tid + str];
            a.x = fminf(a.x, b.x); a.y = fminf(a.y, b.y);
            a.z = fminf(a.z, b.z); a.w = fminf(a.w, b.w);
            s[tid] = a;
        }
        __syncthreads();
    }

    if (tid < 16) {
        reinterpret_cast<float4*>(g_ypart)[(size_t)(chunk * 256 + pair) * 16 + tid] = s[tid];
    }
}

__global__ __launch_bounds__(256) void ky_final(float* __restrict__ out) {
    const int i = blockIdx.x * 256 + threadIdx.x;   // 0..16383 (pair*64 + h)
    float m = INFF;
    #pragma unroll
    for (int c = 0; c < 8; c++) m = fminf(m, g_ypart[c * 16384 + i]);
    out[i] = m;
}

// ---------------------------------------------------------------------------
// Kernel 3: z top-3 with indices. Warp per row (131072 rows of 512 floats).
// ---------------------------------------------------------------------------
__global__ __launch_bounds__(256) void kz_top3(const float* __restrict__ z,
                                               float* __restrict__ zval,
                                               float* __restrict__ zidx) {
    const int row  = blockIdx.x * 8 + (threadIdx.x >> 5);
    const int lane = threadIdx.x & 31;
    const float4* p = reinterpret_cast<const float4*>(z) + (size_t)row * 128;

    float v0 = NINFF, v1 = NINFF, v2 = NINFF;
    int   i0 = 0x3fffffff, i1 = 0x3fffffff, i2 = 0x3fffffff;

    #pragma unroll
    for (int k = 0; k < 4; k++) {
        float4 q = p[lane + k * 32];
        const int base = (lane + k * 32) * 4;
        INS3(q.x, base);     INS3(q.y, base + 1);
        INS3(q.z, base + 2); INS3(q.w, base + 3);
    }

    #pragma unroll
    for (int off = 16; off; off >>= 1) {
        float w0 = __shfl_xor_sync(0xffffffffu, v0, off);
        float w1 = __shfl_xor_sync(0xffffffffu, v1, off);
        float w2 = __shfl_xor_sync(0xffffffffu, v2, off);
        int   j0 = __shfl_xor_sync(0xffffffffu, i0, off);
        int   j1 = __shfl_xor_sync(0xffffffffu, i1, off);
        int   j2 = __shfl_xor_sync(0xffffffffu, i2, off);
        INS3(w0, j0); INS3(w1, j1); INS3(w2, j2);
    }

    if (lane == 0) {
        const size_t o = (size_t)row * 3;
        zval[o + 0] = v0; zval[o + 1] = v1; zval[o + 2] = v2;
        zidx[o + 0] = (float)i0; zidx[o + 1] = (float)i1; zidx[o + 2] = (float)i2;
    }
}

// ---------------------------------------------------------------------------
// Launch. Output layout (float32, concatenated reference tuple):
//   [0,       262144) x_top   [32,2048,4]
//   [262144,  278528) y_min   [8,32,1,64]
//   [278528,  671744) z_top   [32,4096,3]
//   [671744, 1064960) z_idx   [32,4096,3] (as float)
// ---------------------------------------------------------------------------
extern "C" void kernel_launch(void* const* d_in, const int* in_sizes, int n_in,
                              void* d_out, int out_size) {
    const float* x = (const float*)d_in[0];   // 32*2048*1024
    const float* y = (const float*)d_in[1];   // 8*32*2048*64
    const float* z = (const float*)d_in[2];   // 32*4096*512

    float* out   = (float*)d_out;
    float* x_out = out;
    float* y_out = out + 262144;
    float* z_val = out + 278528;
    float* z_idx = out + 671744;

    kx_top4   <<<8192, 256>>>(x, x_out);
    ky_partial<<<dim3(256, 8), 256>>>(y);
    ky_final  <<<64, 256>>>(y_out);
    kz_top3   <<<16384, 256>>>(z, z_val, z_idx);
}

// round 8
// speedup vs baseline: 2.7969x; 2.7969x over previous
#include <cuda_runtime.h>
#include <cstdint>

// ---------------------------------------------------------------------------
// Fused top-k triple (branchless rewrite):
//   x: [32,2048,1024] f32 -> top-4 desc per row
//   y: [8,32,2048,64] f32 -> min over dim2 (2048)
//   z: [32,4096,512]  f32 -> top-3 desc values + indices (stable, lower idx wins)
// Output f32 layout: x_top[262144] | y_min[16384] | z_top[393216] | z_idx[393216]
//
// R7 lesson: branchy guarded inserts were issue-bound (~120 instr / 32-elem
// group). This version: FMNMX networks (x), FSETP+SEL inserts (z), REDUX-based
// warp merges, single fused kernel + tiny y-final kernel.
// ---------------------------------------------------------------------------

#define INFF  (__int_as_float(0x7f800000))
#define NINFF (__int_as_float(0xff800000))

// Order-preserving float<->uint mapping (no NaNs in randn inputs).
__device__ __forceinline__ unsigned f2mono(float f) {
    unsigned b = __float_as_uint(f);
    return b ^ ((unsigned)(((int)b) >> 31) | 0x80000000u);
}
__device__ __forceinline__ float mono2f(unsigned u) {
    unsigned mask = ((unsigned)((~(int)u) >> 31)) | 0x80000000u;
    return __uint_as_float(u ^ mask);
}

// Branchless sorted-descending top-4 insert (values only): 7 FMNMX.
#define XINS(w_) do { float _w = (w_);                     \
    float _a = fmaxf(_w, v0); float _b = fminf(_w, v0);    \
    float _c = fmaxf(_b, v1); float _d = fminf(_b, v1);    \
    float _e = fmaxf(_d, v2); float _f = fminf(_d, v2);    \
    v0 = _a; v1 = _c; v2 = _e; v3 = fmaxf(_f, v3); } while (0)

// Branchless sorted-descending top-3 insert with index.
// Strict > with ascending-index processing == jax.lax.top_k stability.
#define ZINS(w_, wi_) do { float _w = (w_); int _wi = (wi_);              \
    bool _g0 = _w > v0, _g1 = _w > v1, _g2 = _w > v2;                     \
    float _nv1 = _g1 ? (_g0 ? v0 : _w) : v1;                              \
    int   _ni1 = _g1 ? (_g0 ? i0 : _wi) : i1;                             \
    float _nv2 = _g2 ? (_g1 ? v1 : _w) : v2;                              \
    int   _ni2 = _g2 ? (_g1 ? i1 : _wi) : i2;                             \
    v0 = _g0 ? _w : v0;  i0 = _g0 ? _wi : i0;                             \
    v1 = _nv1; i1 = _ni1; v2 = _nv2; i2 = _ni2; } while (0)

__device__ float g_ypart[8 * 256 * 64];

// ---------------------------------------------------------------------------
// Mega kernel: block dispatch
//   [0,     16384) -> z top-3      (warp/row, 131072 rows of 512)
//   [16384, 24576) -> x top-4      (warp/row, 65536 rows of 1024)
//   [24576, 26624) -> y partial min (block per (pair, t-chunk))
// ---------------------------------------------------------------------------
__global__ __launch_bounds__(256) void mega(const float* __restrict__ x,
                                            const float* __restrict__ y,
                                            const float* __restrict__ z,
                                            float* __restrict__ x_out,
                                            float* __restrict__ z_val,
                                            float* __restrict__ z_idx) {
    const int bid = blockIdx.x;
    const int tid = threadIdx.x;
    __shared__ float4 s[256];

    if (bid < 16384) {
        // ---------------- z: top-3 values + indices ----------------
        const int row  = bid * 8 + (tid >> 5);
        const int lane = tid & 31;
        const float4* p = reinterpret_cast<const float4*>(z) + (size_t)row * 128;

        float v0 = NINFF, v1 = NINFF, v2 = NINFF;
        int   i0 = 0, i1 = 0, i2 = 0;
        const int il = lane * 4;

        #pragma unroll
        for (int k = 0; k < 4; k++) {
            float4 q = p[lane + k * 32];
            const int base = il + k * 128;      // element idx = 4*(lane+32k)+c
            ZINS(q.x, base + 0);
            ZINS(q.y, base + 1);
            ZINS(q.z, base + 2);
            ZINS(q.w, base + 3);
        }

        // Warp merge via REDUX rounds on monotone keys.
        unsigned m0 = f2mono(v0), m1 = f2mono(v1), m2 = f2mono(v2);
        unsigned bv[3], bi[3];
        #pragma unroll
        for (int r = 0; r < 3; r++) {
            unsigned best = __reduce_max_sync(0xffffffffu, m0);
            unsigned cand = (m0 == best) ? (unsigned)i0 : 0xffffffffu;
            unsigned bidx = __reduce_min_sync(0xffffffffu, cand);
            bool pop = (m0 == best) && ((unsigned)i0 == bidx);
            m0 = pop ? m1 : m0;  i0 = pop ? i1 : i0;
            m1 = pop ? m2 : m1;  i1 = pop ? i2 : i1;
            m2 = pop ? 0u : m2;
            bv[r] = best; bi[r] = bidx;
        }

        if (lane == 0) {
            const size_t o = (size_t)row * 3;
            z_val[o + 0] = mono2f(bv[0]);
            z_val[o + 1] = mono2f(bv[1]);
            z_val[o + 2] = mono2f(bv[2]);
            z_idx[o + 0] = (float)bi[0];
            z_idx[o + 1] = (float)bi[1];
            z_idx[o + 2] = (float)bi[2];
        }

    } else if (bid < 24576) {
        // ---------------- x: top-4 values ----------------
        const int row  = (bid - 16384) * 8 + (tid >> 5);
        const int lane = tid & 31;
        const float4* p = reinterpret_cast<const float4*>(x) + (size_t)row * 256;

        float v0 = NINFF, v1 = NINFF, v2 = NINFF, v3 = NINFF;

        #pragma unroll
        for (int k = 0; k < 8; k++) {
            float4 q = p[lane + k * 32];
            XINS(q.x); XINS(q.y); XINS(q.z); XINS(q.w);
        }

        unsigned m0 = f2mono(v0), m1 = f2mono(v1), m2 = f2mono(v2), m3 = f2mono(v3);
        unsigned bv[4];
        #pragma unroll
        for (int r = 0; r < 4; r++) {
            unsigned best = __reduce_max_sync(0xffffffffu, m0);
            unsigned mask = __ballot_sync(0xffffffffu, m0 == best);
            bool pop = (lane == (__ffs(mask) - 1));   // exactly one lane pops
            m0 = pop ? m1 : m0;
            m1 = pop ? m2 : m1;
            m2 = pop ? m3 : m2;
            m3 = pop ? 0u : m3;
            bv[r] = best;
        }

        if (lane == 0) {
            float4 r;
            r.x = mono2f(bv[0]); r.y = mono2f(bv[1]);
            r.z = mono2f(bv[2]); r.w = mono2f(bv[3]);
            reinterpret_cast<float4*>(x_out)[row] = r;
        }

    } else {
        // ---------------- y: partial min over dim2 ----------------
        const int idx   = bid - 24576;      // 0..2047
        const int pair  = idx & 255;        // b0*32 + b1
        const int chunk = idx >> 8;         // t block of 256
        const int h4    = tid & 15;
        const int tsub  = tid >> 4;

        const float4* p = reinterpret_cast<const float4*>(
            y + ((size_t)pair * 2048 + (size_t)chunk * 256) * 64);

        float4 m; m.x = INFF; m.y = INFF; m.z = INFF; m.w = INFF;

        #pragma unroll 4
        for (int t = tsub; t < 256; t += 16) {
            float4 q = p[t * 16 + h4];
            m.x = fminf(m.x, q.x); m.y = fminf(m.y, q.y);
            m.z = fminf(m.z, q.z); m.w = fminf(m.w, q.w);
        }

        s[tid] = m;
        __syncthreads();

        #pragma unroll
        for (int str = 128; str >= 16; str >>= 1) {
            if (tid < str) {
                float4 a = s[tid], b = s[tid + str];
                a.x = fminf(a.x, b.x); a.y = fminf(a.y, b.y);
                a.z = fminf(a.z, b.z); a.w = fminf(a.w, b.w);
                s[tid] = a;
            }
            __syncthreads();
        }

        if (tid < 16) {
            reinterpret_cast<float4*>(g_ypart)[(size_t)(chunk * 256 + pair) * 16 + tid] = s[tid];
        }
    }
}

__global__ __launch_bounds__(256) void ky_final(float* __restrict__ out) {
    const int i = blockIdx.x * 256 + threadIdx.x;   // 0..16383 (pair*64 + h)
    float m = INFF;
    #pragma unroll
    for (int c = 0; c < 8; c++) m = fminf(m, g_ypart[c * 16384 + i]);
    out[i] = m;
}

// ---------------------------------------------------------------------------
extern "C" void kernel_launch(void* const* d_in, const int* in_sizes, int n_in,
                              void* d_out, int out_size) {
    const float* x = (const float*)d_in[0];   // 32*2048*1024
    const float* y = (const float*)d_in[1];   // 8*32*2048*64
    const float* z = (const float*)d_in[2];   // 32*4096*512

    float* out   = (float*)d_out;
    float* x_out = out;
    float* y_out = out + 262144;
    float* z_val = out + 278528;
    float* z_idx = out + 671744;

    mega    <<<26624, 256>>>(x, y, z, x_out, z_val, z_idx);
    ky_final<<<64, 256>>>(y_out);
}

// round 11
// speedup vs baseline: 3.1454x; 1.1246x over previous
#include <cuda_runtime.h>
#include <cstdint>

// ---------------------------------------------------------------------------
// Fused top-k triple, single kernel:
//   x: [32,2048,1024] f32 -> top-4 desc per row
//   y: [8,32,2048,64] f32 -> min over dim2 (2048)
//   z: [32,4096,512]  f32 -> top-3 desc values + indices (stable, low idx wins)
// Output f32 layout: x_top[262144] | y_min[16384] | z_top[393216] | z_idx[393216]
//
// R8 state: 117.5us, memory-limited. This round: fold y's final reduction into
// the mega kernel (one block per pair, placed first in the grid so the 512KB
// long-poles start in wave 1 and are backfilled by small x/z blocks), drop the
// second launch + scratch round-trip, and use streaming loads (__ldcs) since
// every input byte is read exactly once.
// ---------------------------------------------------------------------------

#define INFF  (__int_as_float(0x7f800000))
#define NINFF (__int_as_float(0xff800000))

__device__ __forceinline__ float4 ldcs4(const float4* p) {
    return __ldcs(p);
}

// Order-preserving float<->uint mapping (no NaNs in randn inputs).
__device__ __forceinline__ unsigned f2mono(float f) {
    unsigned b = __float_as_uint(f);
    return b ^ ((unsigned)(((int)b) >> 31) | 0x80000000u);
}
__device__ __forceinline__ float mono2f(unsigned u) {
    unsigned mask = ((unsigned)((~(int)u) >> 31)) | 0x80000000u;
    return __uint_as_float(u ^ mask);
}

// Branchless sorted-descending top-4 insert (values only): 7 FMNMX.
#define XINS(w_) do { float _w = (w_);                     \
    float _a = fmaxf(_w, v0); float _b = fminf(_w, v0);    \
    float _c = fmaxf(_b, v1); float _d = fminf(_b, v1);    \
    float _e = fmaxf(_d, v2); float _f = fminf(_d, v2);    \
    v0 = _a; v1 = _c; v2 = _e; v3 = fmaxf(_f, v3); } while (0)

// Branchless sorted-descending top-3 insert with index.
// Strict > with ascending-index processing == jax.lax.top_k stability.
#define ZINS(w_, wi_) do { float _w = (w_); int _wi = (wi_);              \
    bool _g0 = _w > v0, _g1 = _w > v1, _g2 = _w > v2;                     \
    float _nv1 = _g1 ? (_g0 ? v0 : _w) : v1;                              \
    int   _ni1 = _g1 ? (_g0 ? i0 : _wi) : i1;                             \
    float _nv2 = _g2 ? (_g1 ? v1 : _w) : v2;                              \
    int   _ni2 = _g2 ? (_g1 ? i1 : _wi) : i2;                             \
    v0 = _g0 ? _w : v0;  i0 = _g0 ? _wi : i0;                             \
    v1 = _nv1; i1 = _ni1; v2 = _nv2; i2 = _ni2; } while (0)

// ---------------------------------------------------------------------------
// Mega kernel: block dispatch (y first: 512KB long-poles start in wave 1)
//   [0,      256) -> y full min     (block per pair, 2048x64 slab)
//   [256,  16640) -> z top-3        (warp/row, 131072 rows of 512)
//   [16640, 24832)-> x top-4        (warp/row, 65536 rows of 1024)
// ---------------------------------------------------------------------------
__global__ __launch_bounds__(256) void mega(const float* __restrict__ x,
                                            const float* __restrict__ y,
                                            const float* __restrict__ z,
                                            float* __restrict__ x_out,
                                            float* __restrict__ y_out,
                                            float* __restrict__ z_val,
                                            float* __restrict__ z_idx) {
    const int bid = blockIdx.x;
    const int tid = threadIdx.x;
    __shared__ float4 s[256];

    if (bid < 256) {
        // ---------------- y: full min over dim2 (one block per pair) -------
        const int pair = bid;              // b0*32 + b1
        const int h4   = tid & 15;         // float4 column group (h = 4*h4..)
        const int tsub = tid >> 4;         // 0..15 (t stripe)

        const float4* p = reinterpret_cast<const float4*>(y)
                        + (size_t)pair * 2048 * 16;

        float4 m; m.x = INFF; m.y = INFF; m.z = INFF; m.w = INFF;

        #pragma unroll 8
        for (int t = tsub; t < 2048; t += 16) {
            float4 q = ldcs4(p + t * 16 + h4);
            m.x = fminf(m.x, q.x); m.y = fminf(m.y, q.y);
            m.z = fminf(m.z, q.z); m.w = fminf(m.w, q.w);
        }

        s[tid] = m;
        __syncthreads();

        #pragma unroll
        for (int str = 128; str >= 16; str >>= 1) {
            if (tid < str) {
                float4 a = s[tid], b = s[tid + str];
                a.x = fminf(a.x, b.x); a.y = fminf(a.y, b.y);
                a.z = fminf(a.z, b.z); a.w = fminf(a.w, b.w);
                s[tid] = a;
            }
            __syncthreads();
        }

        if (tid < 16) {
            reinterpret_cast<float4*>(y_out)[pair * 16 + tid] = s[tid];
        }

    } else if (bid < 16640) {
        // ---------------- z: top-3 values + indices ----------------
        const int row  = (bid - 256) * 8 + (tid >> 5);
        const int lane = tid & 31;
        const float4* p = reinterpret_cast<const float4*>(z) + (size_t)row * 128;

        float v0 = NINFF, v1 = NINFF, v2 = NINFF;
        int   i0 = 0, i1 = 0, i2 = 0;
        const int il = lane * 4;

        #pragma unroll
        for (int k = 0; k < 4; k++) {
            float4 q = ldcs4(p + lane + k * 32);
            const int base = il + k * 128;      // element idx = 4*(lane+32k)+c
            ZINS(q.x, base + 0);
            ZINS(q.y, base + 1);
            ZINS(q.z, base + 2);
            ZINS(q.w, base + 3);
        }

        // Warp merge via REDUX rounds on monotone keys.
        unsigned m0 = f2mono(v0), m1 = f2mono(v1), m2 = f2mono(v2);
        unsigned bv[3], bi[3];
        #pragma unroll
        for (int r = 0; r < 3; r++) {
            unsigned best = __reduce_max_sync(0xffffffffu, m0);
            unsigned cand = (m0 == best) ? (unsigned)i0 : 0xffffffffu;
            unsigned bidx = __reduce_min_sync(0xffffffffu, cand);
            bool pop = (m0 == best) && ((unsigned)i0 == bidx);
            m0 = pop ? m1 : m0;  i0 = pop ? i1 : i0;
            m1 = pop ? m2 : m1;  i1 = pop ? i2 : i1;
            m2 = pop ? 0u : m2;
            bv[r] = best; bi[r] = bidx;
        }

        if (lane == 0) {
            const size_t o = (size_t)row * 3;
            z_val[o + 0] = mono2f(bv[0]);
            z_val[o + 1] = mono2f(bv[1]);
            z_val[o + 2] = mono2f(bv[2]);
            z_idx[o + 0] = (float)bi[0];
            z_idx[o + 1] = (float)bi[1];
            z_idx[o + 2] = (float)bi[2];
        }

    } else {
        // ---------------- x: top-4 values ----------------
        const int row  = (bid - 16640) * 8 + (tid >> 5);
        const int lane = tid & 31;
        const float4* p = reinterpret_cast<const float4*>(x) + (size_t)row * 256;

        float v0 = NINFF, v1 = NINFF, v2 = NINFF, v3 = NINFF;

        #pragma unroll
        for (int k = 0; k < 8; k++) {
            float4 q = ldcs4(p + lane + k * 32);
            XINS(q.x); XINS(q.y); XINS(q.z); XINS(q.w);
        }

        unsigned m0 = f2mono(v0), m1 = f2mono(v1), m2 = f2mono(v2), m3 = f2mono(v3);
        unsigned bv[4];
        #pragma unroll
        for (int r = 0; r < 4; r++) {
            unsigned best = __reduce_max_sync(0xffffffffu, m0);
            unsigned mask = __ballot_sync(0xffffffffu, m0 == best);
            bool pop = (lane == (__ffs(mask) - 1));   // exactly one lane pops
            m0 = pop ? m1 : m0;
            m1 = pop ? m2 : m1;
            m2 = pop ? m3 : m2;
            m3 = pop ? 0u : m3;
            bv[r] = best;
        }

        if (lane == 0) {
            float4 r;
            r.x = mono2f(bv[0]); r.y = mono2f(bv[1]);
            r.z = mono2f(bv[2]); r.w = mono2f(bv[3]);
            reinterpret_cast<float4*>(x_out)[row] = r;
        }
    }
}

// ---------------------------------------------------------------------------
extern "C" void kernel_launch(void* const* d_in, const int* in_sizes, int n_in,
                              void* d_out, int out_size) {
    const float* x = (const float*)d_in[0];   // 32*2048*1024
    const float* y = (const float*)d_in[1];   // 8*32*2048*64
    const float* z = (const float*)d_in[2];   // 32*4096*512

    float* out   = (float*)d_out;
    float* x_out = out;
    float* y_out = out + 262144;
    float* z_val = out + 278528;
    float* z_idx = out + 671744;

    mega<<<24832, 256>>>(x, y, z, x_out, y_out, z_val, z_idx);
}